// round 5
// baseline (speedup 1.0000x reference)
#include <cuda_runtime.h>
#include <cuda_bf16.h>
#include <math.h>

// ---------------------------------------------------------------------------
// LLaDA router: logits = x @ W^T  (N tokens, D feat, E=8 experts)
//   -> LayerNorm(E) -> /(|T|+1e-6) -> softmax -> top-2 dispatch
//   -> router_loss = 0.01*mean(rl^2) + 0.01*KL(ideal||actual)/E
// Out layout: [routing_weights N*E][dispatch N*E][loss 1]
//
// cp.async multistage pipeline: x staged through a 4-deep smem ring (16KB
// stages), compute reads LDS.128; W stays L1-resident via __ldg. f32x2
// accumulators packed over d-parity (operands are adjacent LDS/LDG pairs).
// ---------------------------------------------------------------------------

#define EXPERTS 8
#define TOK_PER_WARP 4
#define WARPS_PER_BLOCK 8
#define TOK_PER_BLOCK (TOK_PER_WARP * WARPS_PER_BLOCK)   // 32
#define MAX_BLOCKS 8192
#define STAGES 4
#define STAGE_FLOATS 128                                  // d-span per stage
#define STAGE_BYTES (TOK_PER_BLOCK * STAGE_FLOATS * 4)    // 16384
#define TOK_ROW_BYTES (STAGE_FLOATS * 4)                  // 512

__device__ float g_part[MAX_BLOCKS * 9];
__device__ unsigned int g_ctr = 0;

typedef unsigned long long u64;

__device__ __forceinline__ void fma2p(u64& acc, float xlo, float xhi,
                                      float wlo, float whi) {
    asm("{\n\t"
        ".reg .b64 xp, wp;\n\t"
        "mov.b64 xp, {%1, %2};\n\t"
        "mov.b64 wp, {%3, %4};\n\t"
        "fma.rn.f32x2 %0, xp, wp, %0;\n\t"
        "}"
        : "+l"(acc) : "f"(xlo), "f"(xhi), "f"(wlo), "f"(whi));
}
__device__ __forceinline__ void unpk2(u64 v, float& lo, float& hi) {
    asm("mov.b64 {%0, %1}, %2;" : "=f"(lo), "=f"(hi) : "l"(v));
}
__device__ __forceinline__ unsigned int smem_u32(const void* p) {
    return (unsigned int)__cvta_generic_to_shared(p);
}
__device__ __forceinline__ void cp16(unsigned int dst, const void* src) {
    asm volatile("cp.async.cg.shared.global [%0], [%1], 16;"
                 :: "r"(dst), "l"(src));
}
__device__ __forceinline__ void cp_commit() {
    asm volatile("cp.async.commit_group;");
}
__device__ __forceinline__ void cp_wait2() {
    asm volatile("cp.async.wait_group 2;");
}

template <int DD>   // DD = compile-time D (2048 fast path), 0 = runtime D
__global__ __launch_bounds__(256, 2)
void router_main(const float* __restrict__ x,
                 const float* __restrict__ W,
                 const float* __restrict__ gamma,
                 const float* __restrict__ beta,
                 const float* __restrict__ temp,
                 float* __restrict__ out,
                 int N, int Drt)
{
    const int D = DD ? DD : Drt;
    const int Dq = D >> 2;                       // D in float4 units
    const int nIter = D / STAGE_FLOATS;          // stages to stream

    extern __shared__ char ring[];               // STAGES * 16KB
    __shared__ float s_logits[TOK_PER_BLOCK * EXPERTS];
    __shared__ bool s_last;

    const int lane = threadIdx.x & 31;
    const int warp = threadIdx.x >> 5;
    const int blkTok0 = blockIdx.x * TOK_PER_BLOCK;

    // ---- async stage loader: warp w loads token rows w, w+8, w+16, w+24 ---
    // gmem: x[tok][stage*128 + lane*4 ..+4) ; smem: [tokLocal][lane*16B]
    auto issue_stage = [&](int stage) {
        const size_t dbase = (size_t)stage * STAGE_FLOATS + (lane << 2);
        char* sbase = ring + (size_t)(stage & (STAGES - 1)) * STAGE_BYTES;
#pragma unroll
        for (int sub = 0; sub < 4; ++sub) {
            int tl = warp + sub * WARPS_PER_BLOCK;
            int tok = min(blkTok0 + tl, N - 1);
            const float* g = x + (size_t)tok * D + dbase;
            cp16(smem_u32(sbase + tl * TOK_ROW_BYTES + (lane << 4)), g);
        }
    };

    // prologue: fill 3 stages
    for (int s = 0; s < 3 && s < nIter; ++s) { issue_stage(s); cp_commit(); }

    const float4* wq = (const float4*)W + lane;

    u64 acc[TOK_PER_WARP][EXPERTS];
#pragma unroll
    for (int t = 0; t < TOK_PER_WARP; ++t)
#pragma unroll
        for (int e = 0; e < EXPERTS; ++e) acc[t][e] = 0ull;

    for (int i = 0; i < nIter; ++i) {
        cp_wait2();              // stage i landed
        __syncthreads();         // and every warp finished stage i-1 compute

        if (i + 3 < nIter) issue_stage(i + 3);
        cp_commit();             // unconditional: keeps wait_group count exact

        // compute stage i: warp handles tokens 4*warp .. 4*warp+3
        const char* sbase = ring + (size_t)(i & (STAGES - 1)) * STAGE_BYTES;
        float4 xc[TOK_PER_WARP];
#pragma unroll
        for (int t = 0; t < TOK_PER_WARP; ++t)
            xc[t] = *(const float4*)(sbase +
                     (warp * TOK_PER_WARP + t) * TOK_ROW_BYTES + (lane << 4));

#pragma unroll
        for (int h = 0; h < 2; ++h) {
            float4 wv[4];
#pragma unroll
            for (int e = 0; e < 4; ++e)
                wv[e] = __ldg(wq + (size_t)(h * 4 + e) * Dq + (size_t)i * 32);
#pragma unroll
            for (int t = 0; t < TOK_PER_WARP; ++t)
#pragma unroll
                for (int e = 0; e < 4; ++e) {
                    fma2p(acc[t][h * 4 + e], xc[t].x, xc[t].y, wv[e].x, wv[e].y);
                    fma2p(acc[t][h * 4 + e], xc[t].z, xc[t].w, wv[e].z, wv[e].w);
                }
        }
    }

    // fold d-parity halves, then butterfly-reduce across the warp
    float s[TOK_PER_WARP][EXPERTS];
#pragma unroll
    for (int t = 0; t < TOK_PER_WARP; ++t)
#pragma unroll
        for (int e = 0; e < EXPERTS; ++e) {
            float lo, hi;
            unpk2(acc[t][e], lo, hi);
            s[t][e] = lo + hi;
        }
#pragma unroll
    for (int m = 16; m >= 1; m >>= 1)
#pragma unroll
        for (int t = 0; t < TOK_PER_WARP; ++t)
#pragma unroll
            for (int e = 0; e < EXPERTS; ++e)
                s[t][e] += __shfl_xor_sync(0xFFFFFFFFu, s[t][e], m);

    if (lane == 0) {
#pragma unroll
        for (int t = 0; t < TOK_PER_WARP; ++t)
#pragma unroll
            for (int e = 0; e < EXPERTS; ++e)
                s_logits[(warp * TOK_PER_WARP + t) * EXPERTS + e] = s[t][e];
    }
    __syncthreads();

    // ---- epilogue: warp 0+1 lanes handle the block's 32 tokens ------------
    if (threadIdx.x < TOK_PER_BLOCK) {
        const int lt = threadIdx.x;
        const int g = blkTok0 + lt;
        const bool valid = (g < N);

        const float tinv = 1.0f / (fabsf(temp[0]) + 1e-6f);
        float gm[EXPERTS], bt[EXPERTS];
#pragma unroll
        for (int e = 0; e < EXPERTS; ++e) { gm[e] = gamma[e]; bt[e] = beta[e]; }

        float l[EXPERTS];
        float mu = 0.0f;
#pragma unroll
        for (int e = 0; e < EXPERTS; ++e) {
            l[e] = s_logits[lt * EXPERTS + e];
            mu += l[e];
        }
        mu *= (1.0f / EXPERTS);
        float var = 0.0f;
#pragma unroll
        for (int e = 0; e < EXPERTS; ++e) {
            float dlt = l[e] - mu;
            var += dlt * dlt;
        }
        var *= (1.0f / EXPERTS);
        const float rinv = rsqrtf(var + 1e-5f);

        float rl[EXPERTS];
        float zsum = 0.0f;
        float mx = -1e30f;
#pragma unroll
        for (int e = 0; e < EXPERTS; ++e) {
            float v = ((l[e] - mu) * rinv * gm[e] + bt[e]) * tinv;
            rl[e] = v;
            zsum += v * v;
            mx = fmaxf(mx, v);
        }
        float rw[EXPERTS];
        float ssum = 0.0f;
#pragma unroll
        for (int e = 0; e < EXPERTS; ++e) {
            rw[e] = expf(rl[e] - mx);
            ssum += rw[e];
        }
        const float sinv = 1.0f / ssum;
#pragma unroll
        for (int e = 0; e < EXPERTS; ++e) rw[e] *= sinv;

        // top-2 (lowest index wins ties, matching lax.top_k)
        int i1 = 0; float w1 = rw[0];
#pragma unroll
        for (int e = 1; e < EXPERTS; ++e)
            if (rw[e] > w1) { w1 = rw[e]; i1 = e; }
        int i2 = -1; float w2 = -1.0f;
#pragma unroll
        for (int e = 0; e < EXPERTS; ++e)
            if (e != i1 && rw[e] > w2) { w2 = rw[e]; i2 = e; }
        const float nrm = 1.0f / (w1 + w2 + 1e-6f);
        const float d1 = w1 * nrm, d2 = w2 * nrm;

        if (valid) {
            const size_t NE = (size_t)N * EXPERTS;
            float4* rwo = (float4*)(out + (size_t)g * EXPERTS);
            rwo[0] = make_float4(rw[0], rw[1], rw[2], rw[3]);
            rwo[1] = make_float4(rw[4], rw[5], rw[6], rw[7]);
            float disp[EXPERTS];
#pragma unroll
            for (int e = 0; e < EXPERTS; ++e)
                disp[e] = (e == i1) ? d1 : (e == i2) ? d2 : 0.0f;
            float4* dpo = (float4*)(out + NE + (size_t)g * EXPERTS);
            dpo[0] = make_float4(disp[0], disp[1], disp[2], disp[3]);
            dpo[1] = make_float4(disp[4], disp[5], disp[6], disp[7]);
        }

        // block partials (deterministic: warp reduce then single store)
        float zc = valid ? zsum : 0.0f;
        float ec[EXPERTS];
#pragma unroll
        for (int e = 0; e < EXPERTS; ++e) ec[e] = valid ? rw[e] : 0.0f;

#pragma unroll
        for (int m = 16; m >= 1; m >>= 1) {
            zc += __shfl_xor_sync(0xFFFFFFFFu, zc, m);
#pragma unroll
            for (int e = 0; e < EXPERTS; ++e)
                ec[e] += __shfl_xor_sync(0xFFFFFFFFu, ec[e], m);
        }
        if (lane == 0) {
            float* p = &g_part[(size_t)blockIdx.x * 9];
#pragma unroll
            for (int e = 0; e < EXPERTS; ++e) p[e] = ec[e];
            p[8] = zc;
        }
    }

    // ---- fused loss: last block reduces all partials ----------------------
    __syncthreads();
    if (threadIdx.x == 0) {
        __threadfence();
        unsigned int t = atomicAdd(&g_ctr, 1u);
        s_last = (t == gridDim.x - 1);
    }
    __syncthreads();

    if (s_last) {
        __shared__ float s_red[9];
        const int nb = gridDim.x;
        for (int c = warp; c < 9; c += WARPS_PER_BLOCK) {
            float v = 0.0f;
            for (int k = lane; k < nb; k += 32) v += g_part[(size_t)k * 9 + c];
#pragma unroll
            for (int m = 16; m >= 1; m >>= 1)
                v += __shfl_xor_sync(0xFFFFFFFFu, v, m);
            if (lane == 0) s_red[c] = v;
        }
        __syncthreads();
        if (threadIdx.x == 0) {
            const float invN = 1.0f / (float)N;
            float z = s_red[8] * invN * (1.0f / EXPERTS);
            float lb = 0.0f;
            const float ideal = 1.0f / EXPERTS;
#pragma unroll
            for (int e = 0; e < EXPERTS; ++e) {
                float actual = s_red[e] * invN;
                lb += ideal * (logf(ideal) - logf(actual));
            }
            lb *= (1.0f / EXPERTS);
            out[(size_t)2 * N * EXPERTS] = 0.01f * z + 0.01f * lb;
            g_ctr = 0;   // reset for next graph replay (deterministic)
        }
    }
}

extern "C" void kernel_launch(void* const* d_in, const int* in_sizes, int n_in,
                              void* d_out, int out_size)
{
    const float* x     = (const float*)d_in[0];
    const float* W     = (const float*)d_in[1];
    const float* gamma = (const float*)d_in[2];
    const float* beta  = (const float*)d_in[3];
    const float* temp  = (const float*)d_in[4];
    float* out = (float*)d_out;

    const int E = in_sizes[2];           // 8
    const int D = in_sizes[1] / E;       // 2048
    const int N = in_sizes[0] / D;       // 16384

    const int nb = (N + TOK_PER_BLOCK - 1) / TOK_PER_BLOCK;
    const int dynSmem = STAGES * STAGE_BYTES;    // 64 KB

    if (D == 2048) {
        cudaFuncSetAttribute(router_main<2048>,
                             cudaFuncAttributeMaxDynamicSharedMemorySize, dynSmem);
        router_main<2048><<<nb, 256, dynSmem>>>(x, W, gamma, beta, temp, out, N, D);
    } else {
        cudaFuncSetAttribute(router_main<0>,
                             cudaFuncAttributeMaxDynamicSharedMemorySize, dynSmem);
        router_main<0><<<nb, 256, dynSmem>>>(x, W, gamma, beta, temp, out, N, D);
    }
}

// round 6
// speedup vs baseline: 1.2490x; 1.2490x over previous
#include <cuda_runtime.h>
#include <cuda_bf16.h>
#include <math.h>

// ---------------------------------------------------------------------------
// LLaDA router: logits = x @ W^T  (N tokens, D feat, E=8 experts)
//   -> LayerNorm(E) -> /(|T|+1e-6) -> softmax -> top-2 dispatch
//   -> router_loss = 0.01*mean(rl^2) + 0.01*KL(ideal||actual)/E
// Out layout: [routing_weights N*E][dispatch N*E][loss 1]
//
// Occupancy-first design: 2 tokens/warp, expert-pair f32x2 accumulators
// (16 regs), ~63 regs total -> 4 blocks/SM (32 warps). Latency hidden by TLP.
// Fused last-block loss reduction.
// ---------------------------------------------------------------------------

#define EXPERTS 8
#define TOK_PER_WARP 2
#define WARPS_PER_BLOCK 8
#define TOK_PER_BLOCK (TOK_PER_WARP * WARPS_PER_BLOCK)   // 16
#define MAX_BLOCKS 8192

__device__ float g_part[MAX_BLOCKS * 9];
__device__ unsigned int g_ctr = 0;

typedef unsigned long long u64;

__device__ __forceinline__ u64 pk2(float lo, float hi) {
    u64 r;
    asm("mov.b64 %0, {%1, %2};" : "=l"(r) : "f"(lo), "f"(hi));
    return r;
}
__device__ __forceinline__ u64 fma2(u64 a, u64 b, u64 c) {
    u64 d;
    asm("fma.rn.f32x2 %0, %1, %2, %3;" : "=l"(d) : "l"(a), "l"(b), "l"(c));
    return d;
}
__device__ __forceinline__ u64 add2(u64 a, u64 b) {
    u64 d;
    asm("add.rn.f32x2 %0, %1, %2;" : "=l"(d) : "l"(a), "l"(b));
    return d;
}
__device__ __forceinline__ void unpk2(u64 v, float& lo, float& hi) {
    asm("mov.b64 {%0, %1}, %2;" : "=f"(lo), "=f"(hi) : "l"(v));
}
__device__ __forceinline__ float f4c(const float4& v, int d) {
    return (d == 0) ? v.x : (d == 1) ? v.y : (d == 2) ? v.z : v.w;
}

template <int DD>   // DD = compile-time D (2048 fast path), 0 = runtime D
__global__ __launch_bounds__(256, 4)
void router_main(const float* __restrict__ x,
                 const float* __restrict__ W,
                 const float* __restrict__ gamma,
                 const float* __restrict__ beta,
                 const float* __restrict__ temp,
                 float* __restrict__ out,
                 int N, int Drt)
{
    const int D = DD ? DD : Drt;
    const int Dq = D >> 2;                       // D in float4 units

    __shared__ float s_logits[TOK_PER_BLOCK * EXPERTS];
    __shared__ bool s_last;

    const int lane = threadIdx.x & 31;
    const int warp = threadIdx.x >> 5;
    const int tok0 = blockIdx.x * TOK_PER_BLOCK + warp * TOK_PER_WARP;

    const int t0 = min(tok0 + 0, N - 1);         // clamp tail (dup, masked)
    const int t1 = min(tok0 + 1, N - 1);
    const float4* xq0 = (const float4*)x + (size_t)t0 * Dq + lane;
    const float4* xq1 = (const float4*)x + (size_t)t1 * Dq + lane;
    const float4* wq  = (const float4*)W + lane;

    // acc[token][pair j] holds experts (2j, 2j+1) packed in f32x2
    u64 acc[TOK_PER_WARP][EXPERTS / 2];
#pragma unroll
    for (int t = 0; t < TOK_PER_WARP; ++t)
#pragma unroll
        for (int j = 0; j < EXPERTS / 2; ++j) acc[t][j] = 0ull;

    const int nIter = D >> 7;   // warp covers 128 floats per sweep

    for (int i = 0; i < nIter; ++i) {
        const float4 xa = __ldg(xq0 + (size_t)i * 32);
        const float4 xb = __ldg(xq1 + (size_t)i * 32);

        // hoisted x broadcast pairs (shared across both expert halves)
        u64 xx0[4], xx1[4];
#pragma unroll
        for (int d = 0; d < 4; ++d) {
            xx0[d] = pk2(f4c(xa, d), f4c(xa, d));
            xx1[d] = pk2(f4c(xb, d), f4c(xb, d));
        }

#pragma unroll
        for (int h = 0; h < 2; ++h) {           // experts [4h, 4h+4)
            float4 wv[4];
#pragma unroll
            for (int e = 0; e < 4; ++e)
                wv[e] = __ldg(wq + (size_t)(h * 4 + e) * Dq + (size_t)i * 32);

#pragma unroll
            for (int d = 0; d < 4; ++d) {
                u64 wp0 = pk2(f4c(wv[0], d), f4c(wv[1], d));  // e 4h,4h+1
                u64 wp1 = pk2(f4c(wv[2], d), f4c(wv[3], d));  // e 4h+2,4h+3
                acc[0][h * 2 + 0] = fma2(xx0[d], wp0, acc[0][h * 2 + 0]);
                acc[0][h * 2 + 1] = fma2(xx0[d], wp1, acc[0][h * 2 + 1]);
                acc[1][h * 2 + 0] = fma2(xx1[d], wp0, acc[1][h * 2 + 0]);
                acc[1][h * 2 + 1] = fma2(xx1[d], wp1, acc[1][h * 2 + 1]);
            }
        }
    }

    // butterfly reduce 8 packed accumulators across the warp
#pragma unroll
    for (int m = 16; m >= 1; m >>= 1)
#pragma unroll
        for (int t = 0; t < TOK_PER_WARP; ++t)
#pragma unroll
            for (int j = 0; j < EXPERTS / 2; ++j)
                acc[t][j] = add2(acc[t][j],
                                 __shfl_xor_sync(0xFFFFFFFFu, acc[t][j], m));

    if (lane == 0) {
#pragma unroll
        for (int t = 0; t < TOK_PER_WARP; ++t)
#pragma unroll
            for (int j = 0; j < EXPERTS / 2; ++j) {
                float lo, hi;
                unpk2(acc[t][j], lo, hi);
                const int lt = warp * TOK_PER_WARP + t;
                s_logits[lt * EXPERTS + 2 * j + 0] = lo;
                s_logits[lt * EXPERTS + 2 * j + 1] = hi;
            }
    }
    __syncthreads();

    // ---- epilogue: lanes 0..15 of warp 0 handle the block's 16 tokens -----
    if (threadIdx.x < TOK_PER_BLOCK) {
        const int lt = threadIdx.x;
        const int g = blockIdx.x * TOK_PER_BLOCK + lt;
        const bool valid = (g < N);

        const float tinv = 1.0f / (fabsf(temp[0]) + 1e-6f);
        float gm[EXPERTS], bt[EXPERTS];
#pragma unroll
        for (int e = 0; e < EXPERTS; ++e) { gm[e] = gamma[e]; bt[e] = beta[e]; }

        float l[EXPERTS];
        float mu = 0.0f;
#pragma unroll
        for (int e = 0; e < EXPERTS; ++e) {
            l[e] = s_logits[lt * EXPERTS + e];
            mu += l[e];
        }
        mu *= (1.0f / EXPERTS);
        float var = 0.0f;
#pragma unroll
        for (int e = 0; e < EXPERTS; ++e) {
            float dlt = l[e] - mu;
            var += dlt * dlt;
        }
        var *= (1.0f / EXPERTS);
        const float rinv = rsqrtf(var + 1e-5f);

        float rl[EXPERTS];
        float zsum = 0.0f;
        float mx = -1e30f;
#pragma unroll
        for (int e = 0; e < EXPERTS; ++e) {
            float v = ((l[e] - mu) * rinv * gm[e] + bt[e]) * tinv;
            rl[e] = v;
            zsum += v * v;
            mx = fmaxf(mx, v);
        }
        float rw[EXPERTS];
        float ssum = 0.0f;
#pragma unroll
        for (int e = 0; e < EXPERTS; ++e) {
            rw[e] = expf(rl[e] - mx);
            ssum += rw[e];
        }
        const float sinv = 1.0f / ssum;
#pragma unroll
        for (int e = 0; e < EXPERTS; ++e) rw[e] *= sinv;

        // top-2 (lowest index wins ties, matching lax.top_k)
        int i1 = 0; float w1 = rw[0];
#pragma unroll
        for (int e = 1; e < EXPERTS; ++e)
            if (rw[e] > w1) { w1 = rw[e]; i1 = e; }
        int i2 = -1; float w2 = -1.0f;
#pragma unroll
        for (int e = 0; e < EXPERTS; ++e)
            if (e != i1 && rw[e] > w2) { w2 = rw[e]; i2 = e; }
        const float nrm = 1.0f / (w1 + w2 + 1e-6f);
        const float d1 = w1 * nrm, d2 = w2 * nrm;

        if (valid) {
            const size_t NE = (size_t)N * EXPERTS;
            float4* rwo = (float4*)(out + (size_t)g * EXPERTS);
            rwo[0] = make_float4(rw[0], rw[1], rw[2], rw[3]);
            rwo[1] = make_float4(rw[4], rw[5], rw[6], rw[7]);
            float disp[EXPERTS];
#pragma unroll
            for (int e = 0; e < EXPERTS; ++e)
                disp[e] = (e == i1) ? d1 : (e == i2) ? d2 : 0.0f;
            float4* dpo = (float4*)(out + NE + (size_t)g * EXPERTS);
            dpo[0] = make_float4(disp[0], disp[1], disp[2], disp[3]);
            dpo[1] = make_float4(disp[4], disp[5], disp[6], disp[7]);
        }

        // half-warp (16 lanes) reduction of block partials, then single store
        float zc = valid ? zsum : 0.0f;
        float ec[EXPERTS];
#pragma unroll
        for (int e = 0; e < EXPERTS; ++e) ec[e] = valid ? rw[e] : 0.0f;

#pragma unroll
        for (int m = 8; m >= 1; m >>= 1) {
            zc += __shfl_xor_sync(0x0000FFFFu, zc, m);
#pragma unroll
            for (int e = 0; e < EXPERTS; ++e)
                ec[e] += __shfl_xor_sync(0x0000FFFFu, ec[e], m);
        }
        if (lane == 0) {
            float* p = &g_part[(size_t)blockIdx.x * 9];
#pragma unroll
            for (int e = 0; e < EXPERTS; ++e) p[e] = ec[e];
            p[8] = zc;
        }
    }

    // ---- fused loss: last block reduces all partials ----------------------
    __syncthreads();
    if (threadIdx.x == 0) {
        __threadfence();
        unsigned int t = atomicAdd(&g_ctr, 1u);
        s_last = (t == gridDim.x - 1);
    }
    __syncthreads();

    if (s_last) {
        __shared__ float s_red[9];
        const int nb = gridDim.x;
        for (int c = warp; c < 9; c += WARPS_PER_BLOCK) {
            float v = 0.0f;
            for (int k = lane; k < nb; k += 32) v += g_part[(size_t)k * 9 + c];
#pragma unroll
            for (int m = 16; m >= 1; m >>= 1)
                v += __shfl_xor_sync(0xFFFFFFFFu, v, m);
            if (lane == 0) s_red[c] = v;
        }
        __syncthreads();
        if (threadIdx.x == 0) {
            const float invN = 1.0f / (float)N;
            float z = s_red[8] * invN * (1.0f / EXPERTS);
            float lb = 0.0f;
            const float ideal = 1.0f / EXPERTS;
#pragma unroll
            for (int e = 0; e < EXPERTS; ++e) {
                float actual = s_red[e] * invN;
                lb += ideal * (logf(ideal) - logf(actual));
            }
            lb *= (1.0f / EXPERTS);
            out[(size_t)2 * N * EXPERTS] = 0.01f * z + 0.01f * lb;
            g_ctr = 0;   // reset for next graph replay (deterministic)
        }
    }
}

extern "C" void kernel_launch(void* const* d_in, const int* in_sizes, int n_in,
                              void* d_out, int out_size)
{
    const float* x     = (const float*)d_in[0];
    const float* W     = (const float*)d_in[1];
    const float* gamma = (const float*)d_in[2];
    const float* beta  = (const float*)d_in[3];
    const float* temp  = (const float*)d_in[4];
    float* out = (float*)d_out;

    const int E = in_sizes[2];           // 8
    const int D = in_sizes[1] / E;       // 2048
    const int N = in_sizes[0] / D;       // 16384

    const int nb = (N + TOK_PER_BLOCK - 1) / TOK_PER_BLOCK;

    if (D == 2048)
        router_main<2048><<<nb, 256>>>(x, W, gamma, beta, temp, out, N, D);
    else
        router_main<0><<<nb, 256>>>(x, W, gamma, beta, temp, out, N, D);
}